// round 16
// baseline (speedup 1.0000x reference)
#include <cuda_runtime.h>

#define NN 100000
#define EE 1600000
#define FF 128
#define WST2 (128*132)

typedef unsigned long long ull;

__device__ __forceinline__ ull pk2(float a, float b) {
    ull r; asm("mov.b64 %0,{%1,%2};" : "=l"(r) : "f"(a), "f"(b)); return r;
}
__device__ __forceinline__ void up2(ull a, float& lo, float& hi) {
    asm("mov.b64 {%0,%1},%2;" : "=f"(lo), "=f"(hi) : "l"(a));
}
__device__ __forceinline__ void fma2(ull& acc, ull x, ull w) {
    asm("fma.rn.f32x2 %0,%1,%2,%3;" : "=l"(acc) : "l"(x), "l"(w), "l"(acc));
}

// ---------------- device-global scratch ----------------
__device__ float g_q[(size_t)NN * 128];
__device__ float g_k[(size_t)NN * 128];
__device__ float g_m[(size_t)NN * 128];
__device__ float g_p[(size_t)NN * 256];
__device__ float g_acc[(size_t)NN * 128];
__device__ float g_s[(size_t)NN * 256];
__device__ float g_den[(size_t)NN * 2];
__device__ int   g_cnt[NN];
__device__ int   g_off[NN + 1];
__device__ int   g_cur[NN];
__device__ int   g_eid[EE];
__device__ int   g_ssrc[EE];
__device__ float g_wsm[2 * 128 * 64];
__device__ float g_wmT[64 * 256];

// ---------------- sort ----------------
__global__ void hist_kernel(const int* __restrict__ dst) {
    int e = blockIdx.x * blockDim.x + threadIdx.x;
    if (e < EE) atomicAdd(&g_cnt[dst[e]], 1);
}

__global__ void scan_kernel() {
    __shared__ int wsum[32];
    __shared__ int runsh;
    int t = threadIdx.x, lane = t & 31, w = t >> 5;
    if (t == 0) runsh = 0;
    __syncthreads();
    for (int base = 0; base < NN; base += 1024) {
        int runl = runsh;
        int i = base + t;
        int v = 0;
        if (i < NN) { v = g_cnt[i]; g_cnt[i] = 0; }
        int x = v;
        #pragma unroll
        for (int o = 1; o < 32; o <<= 1) {
            int y = __shfl_up_sync(0xffffffffu, x, o);
            if (lane >= o) x += y;
        }
        if (lane == 31) wsum[w] = x;
        __syncthreads();
        if (w == 0) {
            int s = wsum[lane];
            #pragma unroll
            for (int o = 1; o < 32; o <<= 1) {
                int y = __shfl_up_sync(0xffffffffu, s, o);
                if (lane >= o) s += y;
            }
            wsum[lane] = s;
        }
        __syncthreads();
        int excl = runl + (w ? wsum[w - 1] : 0) + x - v;
        if (i < NN) { g_off[i] = excl; g_cur[i] = excl; }
        int total = wsum[31];
        __syncthreads();
        if (t == 0) runsh = runl + total;
        __syncthreads();
    }
    if (t == 0) g_off[NN] = runsh;
}

__global__ void scatter_kernel(const int* __restrict__ dst, const int* __restrict__ src) {
    int e = blockIdx.x * blockDim.x + threadIdx.x;
    if (e < EE) {
        int pos = atomicAdd(&g_cur[dst[e]], 1);
        g_eid[pos] = e;
        g_ssrc[pos] = src[e];
    }
}

// ------------- weight prep -------------
__global__ void wsm_kernel(const float* __restrict__ wm, const float* __restrict__ whe) {
    int idx = blockIdx.x * blockDim.x + threadIdx.x;
    if (idx >= 2 * 128 * 64) return;
    {
        int o = idx & 63;
        int f = (idx >> 6) & 127;
        int h = idx >> 13;
        float acc = 0.f;
        #pragma unroll 8
        for (int d = 0; d < 64; d++)
            acc += wm[(h * 128 + f) * 64 + d] * whe[(h * 64 + d) * 64 + o];
        g_wsm[idx] = acc;
    }
    {
        int d = idx >> 8, col = idx & 255;
        g_wmT[idx] = wm[col * 64 + d];
    }
}

// ------------- node kernel (R13 proven) -------------
__global__ void __launch_bounds__(512, 1)
node_kernel(const float* __restrict__ ent,
            const float* __restrict__ wq,
            const float* __restrict__ wk,
            const float* __restrict__ wm) {
    extern __shared__ float sm[];
    float* sw = sm;
    float* sf2 = sm + 3 * WST2;
    int t = threadIdx.x;

    for (int i = t; i < 3 * 128 * 128; i += 512) {
        int w = i >> 14;
        int rem = i & 16383;
        int hd = rem >> 7;
        int f = rem & 127;
        int h = hd >> 6, d = hd & 63;
        const float* wp = (w == 0) ? wq : (w == 1) ? wk : wm;
        sw[w * WST2 + hd * 132 + f] = wp[(h * 128 + f) * 64 + d];
    }
    __syncthreads();

    const float* swq = sw;
    const float* swk = sw + WST2;
    const float* swm = sw + 2 * WST2;
    int hd = t & 127, slot = t >> 7;

    for (int grp = blockIdx.x; grp < NN / 32; grp += gridDim.x) {
        int g0 = grp * 32;
        __syncthreads();
        for (int i = t; i < 32 * FF; i += 512) {
            int node = i >> 7, f = i & 127;
            sf2[f * 34 + node] = ent[(size_t)(g0 + node) * FF + f];
        }
        __syncthreads();

        ull aq[4], ak[4], am[4];
        #pragma unroll
        for (int jp = 0; jp < 4; jp++) { aq[jp] = 0; ak[jp] = 0; am[jp] = 0; }

        const float* wqr = swq + hd * 132;
        const float* wkr = swk + hd * 132;
        const float* wmr = swm + hd * 132;

        for (int f4 = 0; f4 < FF; f4 += 4) {
            float wqv[4], wkv[4], wmv[4];
            *(float4*)wqv = *(const float4*)(wqr + f4);
            *(float4*)wkv = *(const float4*)(wkr + f4);
            *(float4*)wmv = *(const float4*)(wmr + f4);
            #pragma unroll
            for (int j = 0; j < 4; j++) {
                ull wq2 = pk2(wqv[j], wqv[j]);
                ull wk2 = pk2(wkv[j], wkv[j]);
                ull wm2 = pk2(wmv[j], wmv[j]);
                const ull* fp = (const ull*)(sf2 + (f4 + j) * 34 + slot * 8);
                #pragma unroll
                for (int jp = 0; jp < 4; jp++) {
                    ull fv = fp[jp];
                    fma2(aq[jp], fv, wq2);
                    fma2(ak[jp], fv, wk2);
                    fma2(am[jp], fv, wm2);
                }
            }
        }

        #pragma unroll
        for (int jp = 0; jp < 4; jp++) {
            int n = g0 + slot * 8 + jp * 2;
            float a0, a1;
            up2(aq[jp], a0, a1);
            g_q[(size_t)n * 128 + hd] = a0; g_q[(size_t)(n + 1) * 128 + hd] = a1;
            up2(ak[jp], a0, a1);
            g_k[(size_t)n * 128 + hd] = a0; g_k[(size_t)(n + 1) * 128 + hd] = a1;
            up2(am[jp], a0, a1);
            g_m[(size_t)n * 128 + hd] = a0; g_m[(size_t)(n + 1) * 128 + hd] = a1;
        }
    }
}

// ------------- p kernel (R14 proven, persistent) -------------
__global__ void __launch_bounds__(256, 2)
p_kernel() {
    extern __shared__ float sm[];
    float* ws = sm;
    float* qs = sm + 64 * 256;
    int t = threadIdx.x;

    for (int i = t; i < 64 * 256; i += 256) ws[i] = g_wmT[i];

    int colq = t & 63, nodeq = t >> 6;
    int col0 = colq * 4;
    int h = col0 >> 7;

    for (int grp = blockIdx.x; grp < NN / 32; grp += gridDim.x) {
        int g0 = grp * 32;
        __syncthreads();
        for (int i = t; i < 32 * 32; i += 256) {
            int node = i >> 5, hq = i & 31;
            float4 v = *(((const float4*)(g_q + (size_t)(g0 + node) * 128)) + hq);
            qs[(hq * 4 + 0) * 34 + node] = v.x;
            qs[(hq * 4 + 1) * 34 + node] = v.y;
            qs[(hq * 4 + 2) * 34 + node] = v.z;
            qs[(hq * 4 + 3) * 34 + node] = v.w;
        }
        __syncthreads();

        ull acc[4][4];
        #pragma unroll
        for (int c = 0; c < 4; c++)
            #pragma unroll
            for (int np = 0; np < 4; np++) acc[c][np] = 0;

        for (int d = 0; d < 64; d++) {
            float4 w4 = *(const float4*)(ws + d * 256 + col0);
            const ull* qp = (const ull*)(qs + (h * 64 + d) * 34 + nodeq * 8);
            ull q0 = qp[0], q1 = qp[1], q2 = qp[2], q3 = qp[3];
            ull w2;
            w2 = pk2(w4.x, w4.x);
            fma2(acc[0][0], q0, w2); fma2(acc[0][1], q1, w2);
            fma2(acc[0][2], q2, w2); fma2(acc[0][3], q3, w2);
            w2 = pk2(w4.y, w4.y);
            fma2(acc[1][0], q0, w2); fma2(acc[1][1], q1, w2);
            fma2(acc[1][2], q2, w2); fma2(acc[1][3], q3, w2);
            w2 = pk2(w4.z, w4.z);
            fma2(acc[2][0], q0, w2); fma2(acc[2][1], q1, w2);
            fma2(acc[2][2], q2, w2); fma2(acc[2][3], q3, w2);
            w2 = pk2(w4.w, w4.w);
            fma2(acc[3][0], q0, w2); fma2(acc[3][1], q1, w2);
            fma2(acc[3][2], q2, w2); fma2(acc[3][3], q3, w2);
        }

        #pragma unroll
        for (int np = 0; np < 4; np++) {
            float x0, x1, y0, y1, z0, z1, w0, w1;
            up2(acc[0][np], x0, x1);
            up2(acc[1][np], y0, y1);
            up2(acc[2][np], z0, z1);
            up2(acc[3][np], w0, w1);
            int n0 = g0 + nodeq * 8 + np * 2;
            *(float4*)(g_p + (size_t)n0 * 256 + col0) = make_float4(x0, y0, z0, w0);
            *(float4*)(g_p + (size_t)(n0 + 1) * 256 + col0) = make_float4(x1, y1, z1, w1);
        }
    }
}

// ------------- edge kernel (proven 355us, UNCHANGED) -------------
__global__ void __launch_bounds__(256)
edge_kernel(const float* __restrict__ rel) {
    int gw = (blockIdx.x * blockDim.x + threadIdx.x) >> 5;
    if (gw >= NN) return;
    int lane = threadIdx.x & 31;
    int n = gw;

    const float4 q4 = *(const float4*)(g_q + (size_t)n * 128 + lane * 4);
    const float4 p0 = *(const float4*)(g_p + (size_t)n * 256 + lane * 4);
    const float4 p1 = *(const float4*)(g_p + (size_t)n * 256 + 128 + lane * 4);

    float4 a4 = {0.f, 0.f, 0.f, 0.f};
    float4 s0 = {0.f, 0.f, 0.f, 0.f};
    float4 s1 = {0.f, 0.f, 0.f, 0.f};
    float den0 = 0.f, den1 = 0.f;

    int i = g_off[n], end = g_off[n + 1];
    if (i >= end) {
        *(float4*)(g_acc + (size_t)n * 128 + lane * 4) = a4;
        *(float4*)(g_s + (size_t)n * 256 + lane * 4) = s0;
        *(float4*)(g_s + (size_t)n * 256 + 128 + lane * 4) = s1;
        if (lane == 0) { g_den[2 * n] = 0.f; g_den[2 * n + 1] = 0.f; }
        return;
    }

    int eA = g_eid[i], sA = g_ssrc[i];
    int i1 = (i + 1 < end) ? i + 1 : i;
    int eB = g_eid[i1], sB = g_ssrc[i1];
    float4 r_n = __ldcs(((const float4*)(rel + (size_t)eA * FF)) + lane);
    float4 k_n = *(const float4*)(g_k + (size_t)sA * 128 + lane * 4);
    float4 m_n = *(const float4*)(g_m + (size_t)sA * 128 + lane * 4);

    while (i < end) {
        float4 r4 = r_n, k4 = k_n, m4 = m_n;
        if (i + 1 < end) {
            r_n = __ldcs(((const float4*)(rel + (size_t)eB * FF)) + lane);
            k_n = *(const float4*)(g_k + (size_t)sB * 128 + lane * 4);
            m_n = *(const float4*)(g_m + (size_t)sB * 128 + lane * 4);
        }
        if (i + 2 < end) {
            eB = g_eid[i + 2];
            sB = g_ssrc[i + 2];
        }
        i++;

        float kqp = k4.x * q4.x + k4.y * q4.y + k4.z * q4.z + k4.w * q4.w;
        float rp0 = r4.x * p0.x + r4.y * p0.y + r4.z * p0.z + r4.w * p0.w;
        float rp1 = r4.x * p1.x + r4.y * p1.y + r4.z * p1.z + r4.w * p1.w;

        #pragma unroll
        for (int o = 16; o > 0; o >>= 1) {
            rp0 += __shfl_xor_sync(0xffffffffu, rp0, o);
            rp1 += __shfl_xor_sync(0xffffffffu, rp1, o);
        }
        float kq = kqp;
        #pragma unroll
        for (int o = 8; o > 0; o >>= 1) kq += __shfl_xor_sync(0xffffffffu, kq, o);
        float kqo = __shfl_xor_sync(0xffffffffu, kq, 16);
        float kq0 = (lane < 16) ? kq : kqo;
        float kq1 = (lane < 16) ? kqo : kq;

        float e0 = kq0 + rp0;
        float e1 = kq1 + rp1;
        e0 = e0 >= 0.f ? e0 : 0.01f * e0;
        e1 = e1 >= 0.f ? e1 : 0.01f * e1;
        float x0 = __expf(e0);
        float x1 = __expf(e1);
        den0 += x0;
        den1 += x1;
        float xm = (lane < 16) ? x0 : x1;
        a4.x += xm * m4.x; a4.y += xm * m4.y; a4.z += xm * m4.z; a4.w += xm * m4.w;
        s0.x += x0 * r4.x; s0.y += x0 * r4.y; s0.z += x0 * r4.z; s0.w += x0 * r4.w;
        s1.x += x1 * r4.x; s1.y += x1 * r4.y; s1.z += x1 * r4.z; s1.w += x1 * r4.w;
    }

    *(float4*)(g_acc + (size_t)n * 128 + lane * 4) = a4;
    *(float4*)(g_s + (size_t)n * 256 + lane * 4) = s0;
    *(float4*)(g_s + (size_t)n * 256 + 128 + lane * 4) = s1;
    if (lane == 0) {
        g_den[2 * n] = den0;
        g_den[2 * n + 1] = den1;
    }
}

// ------------- O1: persistent, 128-node tiles, 4-out x 8-node, conflict-free staging -------------
__global__ void __launch_bounds__(256, 1)
o1_kernel(const float* __restrict__ dial, const float* __restrict__ whd,
          float* __restrict__ out) {
    extern __shared__ float sm[];
    float* wd = sm;                 // 256*64
    float* xb = sm + 256 * 64;      // 256*130
    int t = threadIdx.x;

    for (int i = t; i < 256 * 64; i += 256) wd[i] = whd[i];

    int oq = t & 15, nq = t >> 4;
    int o0 = oq * 4;
    const int NT = (NN + 127) / 128;   // 782

    for (int grp = blockIdx.x; grp < NT; grp += gridDim.x) {
        int g0 = grp * 128;
        __syncthreads();
        // scalar staging: lane = k (coalesced LDG), xb[k*130+node] (2-way STS)
        for (int i = t; i < 128 * 256; i += 256) {
            int node = i >> 8, kq = i & 255;
            int ng = g0 + node; if (ng > NN - 1) ng = NN - 1;
            xb[kq * 130 + node] = dial[(size_t)ng * 256 + kq];
        }
        __syncthreads();

        ull acc[4][4];
        #pragma unroll
        for (int c = 0; c < 4; c++)
            #pragma unroll
            for (int np = 0; np < 4; np++) acc[c][np] = 0;

        #pragma unroll 2
        for (int k = 0; k < 256; k++) {
            float w4[4];
            *(float4*)w4 = *(const float4*)(wd + k * 64 + o0);
            const ull* xp = (const ull*)(xb + k * 130 + nq * 8);
            ull x0 = xp[0], x1 = xp[1], x2 = xp[2], x3 = xp[3];
            #pragma unroll
            for (int c = 0; c < 4; c++) {
                ull w2 = pk2(w4[c], w4[c]);
                fma2(acc[c][0], x0, w2);
                fma2(acc[c][1], x1, w2);
                fma2(acc[c][2], x2, w2);
                fma2(acc[c][3], x3, w2);
            }
        }

        #pragma unroll
        for (int np = 0; np < 4; np++) {
            float lo[4], hi[4];
            #pragma unroll
            for (int c = 0; c < 4; c++) up2(acc[c][np], lo[c], hi[c]);
            int n0 = g0 + nq * 8 + np * 2;
            if (n0 < NN)
                *(float4*)(out + (size_t)n0 * 64 + o0) = make_float4(lo[0], lo[1], lo[2], lo[3]);
            if (n0 + 1 < NN)
                *(float4*)(out + (size_t)(n0 + 1) * 64 + o0) = make_float4(hi[0], hi[1], hi[2], hi[3]);
        }
    }
}

// ------------- O2a: out += (acc/den) @ whe  (K=128, occ 2) -------------
__global__ void __launch_bounds__(256, 2)
o2a_kernel(const float* __restrict__ whe, float* __restrict__ out) {
    extern __shared__ float sm[];
    float* wd = sm;                   // 128*64
    float* xb = sm + 128 * 64;        // 128*130
    float* invs = xb + 128 * 130;     // 256
    int t = threadIdx.x;

    for (int i = t; i < 128 * 64; i += 256) wd[i] = whe[i];

    int oq = t & 15, nq = t >> 4;
    int o0 = oq * 4;
    const int NT = (NN + 127) / 128;

    for (int grp = blockIdx.x; grp < NT; grp += gridDim.x) {
        int g0 = grp * 128;
        __syncthreads();
        for (int i = t; i < 256; i += 256) {
            int node = i >> 1, h = i & 1;
            int ng = g0 + node; if (ng > NN - 1) ng = NN - 1;
            float den = g_den[(size_t)ng * 2 + h];
            invs[i] = (den != 0.f) ? 1.0f / den : 0.f;
        }
        __syncthreads();
        for (int i = t; i < 128 * 128; i += 256) {
            int node = i >> 7, kq = i & 127;
            int ng = g0 + node; if (ng > NN - 1) ng = NN - 1;
            xb[kq * 130 + node] = g_acc[(size_t)ng * 128 + kq] * invs[node * 2 + (kq >> 6)];
        }
        __syncthreads();

        ull acc[4][4];
        #pragma unroll
        for (int c = 0; c < 4; c++)
            #pragma unroll
            for (int np = 0; np < 4; np++) acc[c][np] = 0;

        #pragma unroll 2
        for (int k = 0; k < 128; k++) {
            float w4[4];
            *(float4*)w4 = *(const float4*)(wd + k * 64 + o0);
            const ull* xp = (const ull*)(xb + k * 130 + nq * 8);
            ull x0 = xp[0], x1 = xp[1], x2 = xp[2], x3 = xp[3];
            #pragma unroll
            for (int c = 0; c < 4; c++) {
                ull w2 = pk2(w4[c], w4[c]);
                fma2(acc[c][0], x0, w2);
                fma2(acc[c][1], x1, w2);
                fma2(acc[c][2], x2, w2);
                fma2(acc[c][3], x3, w2);
            }
        }

        #pragma unroll
        for (int np = 0; np < 4; np++) {
            float lo[4], hi[4];
            #pragma unroll
            for (int c = 0; c < 4; c++) up2(acc[c][np], lo[c], hi[c]);
            int n0 = g0 + nq * 8 + np * 2;
            if (n0 < NN) {
                float4 c0 = *(float4*)(out + (size_t)n0 * 64 + o0);
                c0.x += lo[0]; c0.y += lo[1]; c0.z += lo[2]; c0.w += lo[3];
                *(float4*)(out + (size_t)n0 * 64 + o0) = c0;
            }
            if (n0 + 1 < NN) {
                float4 c1 = *(float4*)(out + (size_t)(n0 + 1) * 64 + o0);
                c1.x += hi[0]; c1.y += hi[1]; c1.z += hi[2]; c1.w += hi[3];
                *(float4*)(out + (size_t)(n0 + 1) * 64 + o0) = c1;
            }
        }
    }
}

// ------------- O2b: out += (s/den) @ wsm  (K=256, occ 1) -------------
__global__ void __launch_bounds__(256, 1)
o2b_kernel(float* __restrict__ out) {
    extern __shared__ float sm[];
    float* wd = sm;                   // 256*64
    float* xb = sm + 256 * 64;        // 256*130
    float* invs = xb + 256 * 130;     // 256
    int t = threadIdx.x;

    for (int i = t; i < 256 * 64; i += 256) wd[i] = g_wsm[i];

    int oq = t & 15, nq = t >> 4;
    int o0 = oq * 4;
    const int NT = (NN + 127) / 128;

    for (int grp = blockIdx.x; grp < NT; grp += gridDim.x) {
        int g0 = grp * 128;
        __syncthreads();
        for (int i = t; i < 256; i += 256) {
            int node = i >> 1, h = i & 1;
            int ng = g0 + node; if (ng > NN - 1) ng = NN - 1;
            float den = g_den[(size_t)ng * 2 + h];
            invs[i] = (den != 0.f) ? 1.0f / den : 0.f;
        }
        __syncthreads();
        for (int i = t; i < 128 * 256; i += 256) {
            int node = i >> 8, kq = i & 255;
            int ng = g0 + node; if (ng > NN - 1) ng = NN - 1;
            xb[kq * 130 + node] = g_s[(size_t)ng * 256 + kq] * invs[node * 2 + (kq >> 7)];
        }
        __syncthreads();

        ull acc[4][4];
        #pragma unroll
        for (int c = 0; c < 4; c++)
            #pragma unroll
            for (int np = 0; np < 4; np++) acc[c][np] = 0;

        #pragma unroll 2
        for (int k = 0; k < 256; k++) {
            float w4[4];
            *(float4*)w4 = *(const float4*)(wd + k * 64 + o0);
            const ull* xp = (const ull*)(xb + k * 130 + nq * 8);
            ull x0 = xp[0], x1 = xp[1], x2 = xp[2], x3 = xp[3];
            #pragma unroll
            for (int c = 0; c < 4; c++) {
                ull w2 = pk2(w4[c], w4[c]);
                fma2(acc[c][0], x0, w2);
                fma2(acc[c][1], x1, w2);
                fma2(acc[c][2], x2, w2);
                fma2(acc[c][3], x3, w2);
            }
        }

        #pragma unroll
        for (int np = 0; np < 4; np++) {
            float lo[4], hi[4];
            #pragma unroll
            for (int c = 0; c < 4; c++) up2(acc[c][np], lo[c], hi[c]);
            int n0 = g0 + nq * 8 + np * 2;
            if (n0 < NN) {
                float4 c0 = *(float4*)(out + (size_t)n0 * 64 + o0);
                c0.x += lo[0]; c0.y += lo[1]; c0.z += lo[2]; c0.w += lo[3];
                *(float4*)(out + (size_t)n0 * 64 + o0) = c0;
            }
            if (n0 + 1 < NN) {
                float4 c1 = *(float4*)(out + (size_t)(n0 + 1) * 64 + o0);
                c1.x += hi[0]; c1.y += hi[1]; c1.z += hi[2]; c1.w += hi[3];
                *(float4*)(out + (size_t)(n0 + 1) * 64 + o0) = c1;
            }
        }
    }
}

// ------------------------------- launch --------------------------------------
extern "C" void kernel_launch(void* const* d_in, const int* in_sizes, int n_in,
                              void* d_out, int out_size) {
    const float* ent  = (const float*)d_in[0];
    const float* rel  = (const float*)d_in[1];
    const float* dial = (const float*)d_in[2];
    const float* wm   = (const float*)d_in[3];
    const float* wq   = (const float*)d_in[4];
    const float* wk   = (const float*)d_in[5];
    const float* whe  = (const float*)d_in[6];
    const float* whd  = (const float*)d_in[7];
    const int*   src  = (const int*)d_in[8];
    const int*   dst  = (const int*)d_in[9];
    float* out = (float*)d_out;

    const int NODE_SMEM = (3 * WST2 + 128 * 34) * (int)sizeof(float);
    const int P_SMEM    = (64 * 256 + 128 * 34) * (int)sizeof(float);
    const int O1_SMEM   = (256 * 64 + 256 * 130) * (int)sizeof(float);          // 198,656
    const int O2A_SMEM  = (128 * 64 + 128 * 130 + 256) * (int)sizeof(float);    // 100,352
    const int O2B_SMEM  = (256 * 64 + 256 * 130 + 256) * (int)sizeof(float);    // 199,680

    cudaFuncSetAttribute(node_kernel, cudaFuncAttributeMaxDynamicSharedMemorySize, NODE_SMEM);
    cudaFuncSetAttribute(p_kernel,    cudaFuncAttributeMaxDynamicSharedMemorySize, P_SMEM);
    cudaFuncSetAttribute(o1_kernel,   cudaFuncAttributeMaxDynamicSharedMemorySize, O1_SMEM);
    cudaFuncSetAttribute(o2a_kernel,  cudaFuncAttributeMaxDynamicSharedMemorySize, O2A_SMEM);
    cudaFuncSetAttribute(o2b_kernel,  cudaFuncAttributeMaxDynamicSharedMemorySize, O2B_SMEM);

    node_kernel<<<148, 512, NODE_SMEM>>>(ent, wq, wk, wm);     // (0)
    wsm_kernel<<<(2 * 128 * 64 + 255) / 256, 256>>>(wm, whe);  // (1)
    hist_kernel<<<(EE + 255) / 256, 256>>>(dst);               // (2)
    o1_kernel<<<148, 256, O1_SMEM>>>(dial, whd, out);          // (3) <- profiled slot
    scan_kernel<<<1, 1024>>>();                                // (4)
    scatter_kernel<<<(EE + 255) / 256, 256>>>(dst, src);       // (5)
    p_kernel<<<296, 256, P_SMEM>>>();                          // (6)
    edge_kernel<<<(NN + 7) / 8, 256>>>(rel);                   // (7)
    o2a_kernel<<<296, 256, O2A_SMEM>>>(whe, out);              // (8)
    o2b_kernel<<<148, 256, O2B_SMEM>>>(out);                   // (9)
}

// round 17
// speedup vs baseline: 1.1266x; 1.1266x over previous
#include <cuda_runtime.h>

#define NN 100000
#define EE 1600000
#define FF 128
#define WST2 (128*132)

typedef unsigned long long ull;

__device__ __forceinline__ ull pk2(float a, float b) {
    ull r; asm("mov.b64 %0,{%1,%2};" : "=l"(r) : "f"(a), "f"(b)); return r;
}
__device__ __forceinline__ void up2(ull a, float& lo, float& hi) {
    asm("mov.b64 {%0,%1},%2;" : "=f"(lo), "=f"(hi) : "l"(a));
}
__device__ __forceinline__ void fma2(ull& acc, ull x, ull w) {
    asm("fma.rn.f32x2 %0,%1,%2,%3;" : "=l"(acc) : "l"(x), "l"(w), "l"(acc));
}

// ---------------- device-global scratch ----------------
__device__ float g_q[(size_t)NN * 128];
__device__ float g_k[(size_t)NN * 128];
__device__ float g_m[(size_t)NN * 128];
__device__ float g_p[(size_t)NN * 256];
__device__ float g_acc[(size_t)NN * 128];
__device__ float g_s[(size_t)NN * 256];
__device__ float g_den[(size_t)NN * 2];
__device__ int   g_cnt[NN];
__device__ int   g_off[NN + 1];
__device__ int   g_cur[NN];
__device__ int   g_eid[EE];
__device__ int   g_ssrc[EE];
__device__ float g_wsm[2 * 128 * 64];
__device__ float g_wmT[64 * 256];

// ---------------- sort ----------------
__global__ void hist_kernel(const int* __restrict__ dst) {
    int e = blockIdx.x * blockDim.x + threadIdx.x;
    if (e < EE) atomicAdd(&g_cnt[dst[e]], 1);
}

__global__ void scan_kernel() {
    __shared__ int wsum[32];
    __shared__ int runsh;
    int t = threadIdx.x, lane = t & 31, w = t >> 5;
    if (t == 0) runsh = 0;
    __syncthreads();
    for (int base = 0; base < NN; base += 1024) {
        int runl = runsh;
        int i = base + t;
        int v = 0;
        if (i < NN) { v = g_cnt[i]; g_cnt[i] = 0; }
        int x = v;
        #pragma unroll
        for (int o = 1; o < 32; o <<= 1) {
            int y = __shfl_up_sync(0xffffffffu, x, o);
            if (lane >= o) x += y;
        }
        if (lane == 31) wsum[w] = x;
        __syncthreads();
        if (w == 0) {
            int s = wsum[lane];
            #pragma unroll
            for (int o = 1; o < 32; o <<= 1) {
                int y = __shfl_up_sync(0xffffffffu, s, o);
                if (lane >= o) s += y;
            }
            wsum[lane] = s;
        }
        __syncthreads();
        int excl = runl + (w ? wsum[w - 1] : 0) + x - v;
        if (i < NN) { g_off[i] = excl; g_cur[i] = excl; }
        int total = wsum[31];
        __syncthreads();
        if (t == 0) runsh = runl + total;
        __syncthreads();
    }
    if (t == 0) g_off[NN] = runsh;
}

__global__ void scatter_kernel(const int* __restrict__ dst, const int* __restrict__ src) {
    int e = blockIdx.x * blockDim.x + threadIdx.x;
    if (e < EE) {
        int pos = atomicAdd(&g_cur[dst[e]], 1);
        g_eid[pos] = e;
        g_ssrc[pos] = src[e];
    }
}

// ------------- weight prep -------------
__global__ void wsm_kernel(const float* __restrict__ wm, const float* __restrict__ whe) {
    int idx = blockIdx.x * blockDim.x + threadIdx.x;
    if (idx >= 2 * 128 * 64) return;
    {
        int o = idx & 63;
        int f = (idx >> 6) & 127;
        int h = idx >> 13;
        float acc = 0.f;
        #pragma unroll 8
        for (int d = 0; d < 64; d++)
            acc += wm[(h * 128 + f) * 64 + d] * whe[(h * 64 + d) * 64 + o];
        g_wsm[idx] = acc;
    }
    {
        int d = idx >> 8, col = idx & 255;
        g_wmT[idx] = wm[col * 64 + d];
    }
}

// ------------- node kernel (R13 proven) -------------
__global__ void __launch_bounds__(512, 1)
node_kernel(const float* __restrict__ ent,
            const float* __restrict__ wq,
            const float* __restrict__ wk,
            const float* __restrict__ wm) {
    extern __shared__ float sm[];
    float* sw = sm;
    float* sf2 = sm + 3 * WST2;
    int t = threadIdx.x;

    for (int i = t; i < 3 * 128 * 128; i += 512) {
        int w = i >> 14;
        int rem = i & 16383;
        int hd = rem >> 7;
        int f = rem & 127;
        int h = hd >> 6, d = hd & 63;
        const float* wp = (w == 0) ? wq : (w == 1) ? wk : wm;
        sw[w * WST2 + hd * 132 + f] = wp[(h * 128 + f) * 64 + d];
    }
    __syncthreads();

    const float* swq = sw;
    const float* swk = sw + WST2;
    const float* swm = sw + 2 * WST2;
    int hd = t & 127, slot = t >> 7;

    for (int grp = blockIdx.x; grp < NN / 32; grp += gridDim.x) {
        int g0 = grp * 32;
        __syncthreads();
        for (int i = t; i < 32 * FF; i += 512) {
            int node = i >> 7, f = i & 127;
            sf2[f * 34 + node] = ent[(size_t)(g0 + node) * FF + f];
        }
        __syncthreads();

        ull aq[4], ak[4], am[4];
        #pragma unroll
        for (int jp = 0; jp < 4; jp++) { aq[jp] = 0; ak[jp] = 0; am[jp] = 0; }

        const float* wqr = swq + hd * 132;
        const float* wkr = swk + hd * 132;
        const float* wmr = swm + hd * 132;

        for (int f4 = 0; f4 < FF; f4 += 4) {
            float wqv[4], wkv[4], wmv[4];
            *(float4*)wqv = *(const float4*)(wqr + f4);
            *(float4*)wkv = *(const float4*)(wkr + f4);
            *(float4*)wmv = *(const float4*)(wmr + f4);
            #pragma unroll
            for (int j = 0; j < 4; j++) {
                ull wq2 = pk2(wqv[j], wqv[j]);
                ull wk2 = pk2(wkv[j], wkv[j]);
                ull wm2 = pk2(wmv[j], wmv[j]);
                const ull* fp = (const ull*)(sf2 + (f4 + j) * 34 + slot * 8);
                #pragma unroll
                for (int jp = 0; jp < 4; jp++) {
                    ull fv = fp[jp];
                    fma2(aq[jp], fv, wq2);
                    fma2(ak[jp], fv, wk2);
                    fma2(am[jp], fv, wm2);
                }
            }
        }

        #pragma unroll
        for (int jp = 0; jp < 4; jp++) {
            int n = g0 + slot * 8 + jp * 2;
            float a0, a1;
            up2(aq[jp], a0, a1);
            g_q[(size_t)n * 128 + hd] = a0; g_q[(size_t)(n + 1) * 128 + hd] = a1;
            up2(ak[jp], a0, a1);
            g_k[(size_t)n * 128 + hd] = a0; g_k[(size_t)(n + 1) * 128 + hd] = a1;
            up2(am[jp], a0, a1);
            g_m[(size_t)n * 128 + hd] = a0; g_m[(size_t)(n + 1) * 128 + hd] = a1;
        }
    }
}

// ------------- p kernel (R14 proven, persistent) -------------
__global__ void __launch_bounds__(256, 2)
p_kernel() {
    extern __shared__ float sm[];
    float* ws = sm;
    float* qs = sm + 64 * 256;
    int t = threadIdx.x;

    for (int i = t; i < 64 * 256; i += 256) ws[i] = g_wmT[i];

    int colq = t & 63, nodeq = t >> 6;
    int col0 = colq * 4;
    int h = col0 >> 7;

    for (int grp = blockIdx.x; grp < NN / 32; grp += gridDim.x) {
        int g0 = grp * 32;
        __syncthreads();
        for (int i = t; i < 32 * 32; i += 256) {
            int node = i >> 5, hq = i & 31;
            float4 v = *(((const float4*)(g_q + (size_t)(g0 + node) * 128)) + hq);
            qs[(hq * 4 + 0) * 34 + node] = v.x;
            qs[(hq * 4 + 1) * 34 + node] = v.y;
            qs[(hq * 4 + 2) * 34 + node] = v.z;
            qs[(hq * 4 + 3) * 34 + node] = v.w;
        }
        __syncthreads();

        ull acc[4][4];
        #pragma unroll
        for (int c = 0; c < 4; c++)
            #pragma unroll
            for (int np = 0; np < 4; np++) acc[c][np] = 0;

        for (int d = 0; d < 64; d++) {
            float4 w4 = *(const float4*)(ws + d * 256 + col0);
            const ull* qp = (const ull*)(qs + (h * 64 + d) * 34 + nodeq * 8);
            ull q0 = qp[0], q1 = qp[1], q2 = qp[2], q3 = qp[3];
            ull w2;
            w2 = pk2(w4.x, w4.x);
            fma2(acc[0][0], q0, w2); fma2(acc[0][1], q1, w2);
            fma2(acc[0][2], q2, w2); fma2(acc[0][3], q3, w2);
            w2 = pk2(w4.y, w4.y);
            fma2(acc[1][0], q0, w2); fma2(acc[1][1], q1, w2);
            fma2(acc[1][2], q2, w2); fma2(acc[1][3], q3, w2);
            w2 = pk2(w4.z, w4.z);
            fma2(acc[2][0], q0, w2); fma2(acc[2][1], q1, w2);
            fma2(acc[2][2], q2, w2); fma2(acc[2][3], q3, w2);
            w2 = pk2(w4.w, w4.w);
            fma2(acc[3][0], q0, w2); fma2(acc[3][1], q1, w2);
            fma2(acc[3][2], q2, w2); fma2(acc[3][3], q3, w2);
        }

        #pragma unroll
        for (int np = 0; np < 4; np++) {
            float x0, x1, y0, y1, z0, z1, w0, w1;
            up2(acc[0][np], x0, x1);
            up2(acc[1][np], y0, y1);
            up2(acc[2][np], z0, z1);
            up2(acc[3][np], w0, w1);
            int n0 = g0 + nodeq * 8 + np * 2;
            *(float4*)(g_p + (size_t)n0 * 256 + col0) = make_float4(x0, y0, z0, w0);
            *(float4*)(g_p + (size_t)(n0 + 1) * 256 + col0) = make_float4(x1, y1, z1, w1);
        }
    }
}

// ------------- edge kernel (proven 355us, UNCHANGED) -------------
__global__ void __launch_bounds__(256)
edge_kernel(const float* __restrict__ rel) {
    int gw = (blockIdx.x * blockDim.x + threadIdx.x) >> 5;
    if (gw >= NN) return;
    int lane = threadIdx.x & 31;
    int n = gw;

    const float4 q4 = *(const float4*)(g_q + (size_t)n * 128 + lane * 4);
    const float4 p0 = *(const float4*)(g_p + (size_t)n * 256 + lane * 4);
    const float4 p1 = *(const float4*)(g_p + (size_t)n * 256 + 128 + lane * 4);

    float4 a4 = {0.f, 0.f, 0.f, 0.f};
    float4 s0 = {0.f, 0.f, 0.f, 0.f};
    float4 s1 = {0.f, 0.f, 0.f, 0.f};
    float den0 = 0.f, den1 = 0.f;

    int i = g_off[n], end = g_off[n + 1];
    if (i >= end) {
        *(float4*)(g_acc + (size_t)n * 128 + lane * 4) = a4;
        *(float4*)(g_s + (size_t)n * 256 + lane * 4) = s0;
        *(float4*)(g_s + (size_t)n * 256 + 128 + lane * 4) = s1;
        if (lane == 0) { g_den[2 * n] = 0.f; g_den[2 * n + 1] = 0.f; }
        return;
    }

    int eA = g_eid[i], sA = g_ssrc[i];
    int i1 = (i + 1 < end) ? i + 1 : i;
    int eB = g_eid[i1], sB = g_ssrc[i1];
    float4 r_n = __ldcs(((const float4*)(rel + (size_t)eA * FF)) + lane);
    float4 k_n = *(const float4*)(g_k + (size_t)sA * 128 + lane * 4);
    float4 m_n = *(const float4*)(g_m + (size_t)sA * 128 + lane * 4);

    while (i < end) {
        float4 r4 = r_n, k4 = k_n, m4 = m_n;
        if (i + 1 < end) {
            r_n = __ldcs(((const float4*)(rel + (size_t)eB * FF)) + lane);
            k_n = *(const float4*)(g_k + (size_t)sB * 128 + lane * 4);
            m_n = *(const float4*)(g_m + (size_t)sB * 128 + lane * 4);
        }
        if (i + 2 < end) {
            eB = g_eid[i + 2];
            sB = g_ssrc[i + 2];
        }
        i++;

        float kqp = k4.x * q4.x + k4.y * q4.y + k4.z * q4.z + k4.w * q4.w;
        float rp0 = r4.x * p0.x + r4.y * p0.y + r4.z * p0.z + r4.w * p0.w;
        float rp1 = r4.x * p1.x + r4.y * p1.y + r4.z * p1.z + r4.w * p1.w;

        #pragma unroll
        for (int o = 16; o > 0; o >>= 1) {
            rp0 += __shfl_xor_sync(0xffffffffu, rp0, o);
            rp1 += __shfl_xor_sync(0xffffffffu, rp1, o);
        }
        float kq = kqp;
        #pragma unroll
        for (int o = 8; o > 0; o >>= 1) kq += __shfl_xor_sync(0xffffffffu, kq, o);
        float kqo = __shfl_xor_sync(0xffffffffu, kq, 16);
        float kq0 = (lane < 16) ? kq : kqo;
        float kq1 = (lane < 16) ? kqo : kq;

        float e0 = kq0 + rp0;
        float e1 = kq1 + rp1;
        e0 = e0 >= 0.f ? e0 : 0.01f * e0;
        e1 = e1 >= 0.f ? e1 : 0.01f * e1;
        float x0 = __expf(e0);
        float x1 = __expf(e1);
        den0 += x0;
        den1 += x1;
        float xm = (lane < 16) ? x0 : x1;
        a4.x += xm * m4.x; a4.y += xm * m4.y; a4.z += xm * m4.z; a4.w += xm * m4.w;
        s0.x += x0 * r4.x; s0.y += x0 * r4.y; s0.z += x0 * r4.z; s0.w += x0 * r4.w;
        s1.x += x1 * r4.x; s1.y += x1 * r4.y; s1.z += x1 * r4.z; s1.w += x1 * r4.w;
    }

    *(float4*)(g_acc + (size_t)n * 128 + lane * 4) = a4;
    *(float4*)(g_s + (size_t)n * 256 + lane * 4) = s0;
    *(float4*)(g_s + (size_t)n * 256 + 128 + lane * 4) = s1;
    if (lane == 0) {
        g_den[2 * n] = den0;
        g_den[2 * n + 1] = den1;
    }
}

// ------------- O1: R15 proven version (129us): 64-node tiles, 4x4, float4 staging -------------
__global__ void __launch_bounds__(256, 1)
o1_kernel(const float* __restrict__ dial, const float* __restrict__ whd,
          float* __restrict__ out) {
    extern __shared__ float sm[];
    float* wd = sm;                 // 256*64
    float* xb = sm + 256 * 64;      // 256*66
    int t = threadIdx.x;

    for (int i = t; i < 256 * 64; i += 256) wd[i] = whd[i];

    int oq = t & 15, nq = t >> 4;
    int o0 = oq * 4;
    const int NT = (NN + 63) / 64;   // 1563

    for (int grp = blockIdx.x; grp < NT; grp += gridDim.x) {
        int g0 = grp * 64;
        __syncthreads();
        for (int i = t; i < 64 * 64; i += 256) {
            int node = i >> 6, kq = i & 63;
            int ng = g0 + node; if (ng > NN - 1) ng = NN - 1;
            float4 v = *(((const float4*)(dial + (size_t)ng * 256)) + kq);
            xb[(kq * 4 + 0) * 66 + node] = v.x;
            xb[(kq * 4 + 1) * 66 + node] = v.y;
            xb[(kq * 4 + 2) * 66 + node] = v.z;
            xb[(kq * 4 + 3) * 66 + node] = v.w;
        }
        __syncthreads();

        ull acc[4][2];
        #pragma unroll
        for (int c = 0; c < 4; c++) { acc[c][0] = 0; acc[c][1] = 0; }

        for (int k = 0; k < 256; k++) {
            float w4[4];
            *(float4*)w4 = *(const float4*)(wd + k * 64 + o0);
            const ull* xp = (const ull*)(xb + k * 66 + nq * 4);
            ull x0 = xp[0], x1 = xp[1];
            #pragma unroll
            for (int c = 0; c < 4; c++) {
                ull w2 = pk2(w4[c], w4[c]);
                fma2(acc[c][0], x0, w2);
                fma2(acc[c][1], x1, w2);
            }
        }

        #pragma unroll
        for (int pp = 0; pp < 2; pp++) {
            float lo[4], hi[4];
            #pragma unroll
            for (int c = 0; c < 4; c++) up2(acc[c][pp], lo[c], hi[c]);
            int n0 = g0 + nq * 4 + pp * 2;
            if (n0 < NN)
                *(float4*)(out + (size_t)n0 * 64 + o0) = make_float4(lo[0], lo[1], lo[2], lo[3]);
            if (n0 + 1 < NN)
                *(float4*)(out + (size_t)(n0 + 1) * 64 + o0) = make_float4(hi[0], hi[1], hi[2], hi[3]);
        }
    }
}

// ------------- O2a: out += (acc/den) @ whe  (K=128, occ 2, float4 staging) -------------
__global__ void __launch_bounds__(256, 2)
o2a_kernel(const float* __restrict__ whe, float* __restrict__ out) {
    extern __shared__ float sm[];
    float* wd = sm;                   // 128*64
    float* xb = sm + 128 * 64;        // 128*130
    float* invs = xb + 128 * 130;     // 256
    int t = threadIdx.x;

    for (int i = t; i < 128 * 64; i += 256) wd[i] = whe[i];

    int oq = t & 15, nq = t >> 4;
    int o0 = oq * 4;
    const int NT = (NN + 127) / 128;

    for (int grp = blockIdx.x; grp < NT; grp += gridDim.x) {
        int g0 = grp * 128;
        __syncthreads();
        for (int i = t; i < 256; i += 256) {
            int node = i >> 1, h = i & 1;
            int ng = g0 + node; if (ng > NN - 1) ng = NN - 1;
            float den = g_den[(size_t)ng * 2 + h];
            invs[i] = (den != 0.f) ? 1.0f / den : 0.f;
        }
        __syncthreads();
        // float4 LDG staging, 4 scalar STS each (row stride 130 keeps 2-way max)
        for (int i = t; i < 128 * 32; i += 256) {
            int node = i >> 5, kq4 = i & 31;
            int ng = g0 + node; if (ng > NN - 1) ng = NN - 1;
            float4 v = *(((const float4*)(g_acc + (size_t)ng * 128)) + kq4);
            float inv = invs[node * 2 + (kq4 >> 4)];
            int k0 = kq4 * 4;
            xb[(k0 + 0) * 130 + node] = v.x * inv;
            xb[(k0 + 1) * 130 + node] = v.y * inv;
            xb[(k0 + 2) * 130 + node] = v.z * inv;
            xb[(k0 + 3) * 130 + node] = v.w * inv;
        }
        __syncthreads();

        ull acc[4][4];
        #pragma unroll
        for (int c = 0; c < 4; c++)
            #pragma unroll
            for (int np = 0; np < 4; np++) acc[c][np] = 0;

        #pragma unroll 2
        for (int k = 0; k < 128; k++) {
            float w4[4];
            *(float4*)w4 = *(const float4*)(wd + k * 64 + o0);
            const ull* xp = (const ull*)(xb + k * 130 + nq * 8);
            ull x0 = xp[0], x1 = xp[1], x2 = xp[2], x3 = xp[3];
            #pragma unroll
            for (int c = 0; c < 4; c++) {
                ull w2 = pk2(w4[c], w4[c]);
                fma2(acc[c][0], x0, w2);
                fma2(acc[c][1], x1, w2);
                fma2(acc[c][2], x2, w2);
                fma2(acc[c][3], x3, w2);
            }
        }

        #pragma unroll
        for (int np = 0; np < 4; np++) {
            float lo[4], hi[4];
            #pragma unroll
            for (int c = 0; c < 4; c++) up2(acc[c][np], lo[c], hi[c]);
            int n0 = g0 + nq * 8 + np * 2;
            if (n0 < NN) {
                float4 c0 = *(float4*)(out + (size_t)n0 * 64 + o0);
                c0.x += lo[0]; c0.y += lo[1]; c0.z += lo[2]; c0.w += lo[3];
                *(float4*)(out + (size_t)n0 * 64 + o0) = c0;
            }
            if (n0 + 1 < NN) {
                float4 c1 = *(float4*)(out + (size_t)(n0 + 1) * 64 + o0);
                c1.x += hi[0]; c1.y += hi[1]; c1.z += hi[2]; c1.w += hi[3];
                *(float4*)(out + (size_t)(n0 + 1) * 64 + o0) = c1;
            }
        }
    }
}

// ------------- O2b: out += (s/den) @ wsm  (K=256, occ 1, float4 staging) -------------
__global__ void __launch_bounds__(256, 1)
o2b_kernel(float* __restrict__ out) {
    extern __shared__ float sm[];
    float* wd = sm;                   // 256*64
    float* xb = sm + 256 * 64;        // 256*130
    float* invs = xb + 256 * 130;     // 256
    int t = threadIdx.x;

    for (int i = t; i < 256 * 64; i += 256) wd[i] = g_wsm[i];

    int oq = t & 15, nq = t >> 4;
    int o0 = oq * 4;
    const int NT = (NN + 127) / 128;

    for (int grp = blockIdx.x; grp < NT; grp += gridDim.x) {
        int g0 = grp * 128;
        __syncthreads();
        for (int i = t; i < 256; i += 256) {
            int node = i >> 1, h = i & 1;
            int ng = g0 + node; if (ng > NN - 1) ng = NN - 1;
            float den = g_den[(size_t)ng * 2 + h];
            invs[i] = (den != 0.f) ? 1.0f / den : 0.f;
        }
        __syncthreads();
        for (int i = t; i < 128 * 64; i += 256) {
            int node = i >> 6, kq4 = i & 63;
            int ng = g0 + node; if (ng > NN - 1) ng = NN - 1;
            float4 v = *(((const float4*)(g_s + (size_t)ng * 256)) + kq4);
            float inv = invs[node * 2 + (kq4 >> 5)];
            int k0 = kq4 * 4;
            xb[(k0 + 0) * 130 + node] = v.x * inv;
            xb[(k0 + 1) * 130 + node] = v.y * inv;
            xb[(k0 + 2) * 130 + node] = v.z * inv;
            xb[(k0 + 3) * 130 + node] = v.w * inv;
        }
        __syncthreads();

        ull acc[4][4];
        #pragma unroll
        for (int c = 0; c < 4; c++)
            #pragma unroll
            for (int np = 0; np < 4; np++) acc[c][np] = 0;

        #pragma unroll 2
        for (int k = 0; k < 256; k++) {
            float w4[4];
            *(float4*)w4 = *(const float4*)(wd + k * 64 + o0);
            const ull* xp = (const ull*)(xb + k * 130 + nq * 8);
            ull x0 = xp[0], x1 = xp[1], x2 = xp[2], x3 = xp[3];
            #pragma unroll
            for (int c = 0; c < 4; c++) {
                ull w2 = pk2(w4[c], w4[c]);
                fma2(acc[c][0], x0, w2);
                fma2(acc[c][1], x1, w2);
                fma2(acc[c][2], x2, w2);
                fma2(acc[c][3], x3, w2);
            }
        }

        #pragma unroll
        for (int np = 0; np < 4; np++) {
            float lo[4], hi[4];
            #pragma unroll
            for (int c = 0; c < 4; c++) up2(acc[c][np], lo[c], hi[c]);
            int n0 = g0 + nq * 8 + np * 2;
            if (n0 < NN) {
                float4 c0 = *(float4*)(out + (size_t)n0 * 64 + o0);
                c0.x += lo[0]; c0.y += lo[1]; c0.z += lo[2]; c0.w += lo[3];
                *(float4*)(out + (size_t)n0 * 64 + o0) = c0;
            }
            if (n0 + 1 < NN) {
                float4 c1 = *(float4*)(out + (size_t)(n0 + 1) * 64 + o0);
                c1.x += hi[0]; c1.y += hi[1]; c1.z += hi[2]; c1.w += hi[3];
                *(float4*)(out + (size_t)(n0 + 1) * 64 + o0) = c1;
            }
        }
    }
}

// ------------------------------- launch --------------------------------------
extern "C" void kernel_launch(void* const* d_in, const int* in_sizes, int n_in,
                              void* d_out, int out_size) {
    const float* ent  = (const float*)d_in[0];
    const float* rel  = (const float*)d_in[1];
    const float* dial = (const float*)d_in[2];
    const float* wm   = (const float*)d_in[3];
    const float* wq   = (const float*)d_in[4];
    const float* wk   = (const float*)d_in[5];
    const float* whe  = (const float*)d_in[6];
    const float* whd  = (const float*)d_in[7];
    const int*   src  = (const int*)d_in[8];
    const int*   dst  = (const int*)d_in[9];
    float* out = (float*)d_out;

    const int NODE_SMEM = (3 * WST2 + 128 * 34) * (int)sizeof(float);
    const int P_SMEM    = (64 * 256 + 128 * 34) * (int)sizeof(float);
    const int O1_SMEM   = (256 * 64 + 256 * 66) * (int)sizeof(float);           // 133,120
    const int O2A_SMEM  = (128 * 64 + 128 * 130 + 256) * (int)sizeof(float);    // 100,352
    const int O2B_SMEM  = (256 * 64 + 256 * 130 + 256) * (int)sizeof(float);    // 199,680

    cudaFuncSetAttribute(node_kernel, cudaFuncAttributeMaxDynamicSharedMemorySize, NODE_SMEM);
    cudaFuncSetAttribute(p_kernel,    cudaFuncAttributeMaxDynamicSharedMemorySize, P_SMEM);
    cudaFuncSetAttribute(o1_kernel,   cudaFuncAttributeMaxDynamicSharedMemorySize, O1_SMEM);
    cudaFuncSetAttribute(o2a_kernel,  cudaFuncAttributeMaxDynamicSharedMemorySize, O2A_SMEM);
    cudaFuncSetAttribute(o2b_kernel,  cudaFuncAttributeMaxDynamicSharedMemorySize, O2B_SMEM);

    node_kernel<<<148, 512, NODE_SMEM>>>(ent, wq, wk, wm);     // (0)
    wsm_kernel<<<(2 * 128 * 64 + 255) / 256, 256>>>(wm, whe);  // (1)
    hist_kernel<<<(EE + 255) / 256, 256>>>(dst);               // (2)
    o1_kernel<<<148, 256, O1_SMEM>>>(dial, whd, out);          // (3) <- profiled slot
    scan_kernel<<<1, 1024>>>();                                // (4)
    scatter_kernel<<<(EE + 255) / 256, 256>>>(dst, src);       // (5)
    p_kernel<<<296, 256, P_SMEM>>>();                          // (6)
    edge_kernel<<<(NN + 7) / 8, 256>>>(rel);                   // (7)
    o2a_kernel<<<296, 256, O2A_SMEM>>>(whe, out);              // (8)
    o2b_kernel<<<148, 256, O2B_SMEM>>>(out);                   // (9)
}